// round 11
// baseline (speedup 1.0000x reference)
#include <cuda_runtime.h>
#include <stdint.h>

// AddRadiusEdgeIndex: dense [N,N] float32 mask (1.0f/0.0f),
// mask[i,j] = (||p_i - p_j|| <= 3), reference-exact fp32 rounding (rel_err==0):
//   sq  = (x*x + y*y) + z*z                       (plain rn mul/add)
//   dot = fmaf(z,z', fmaf(y,y', x*x'))            (gemm k-loop fma chain)
//   d2  = fmaf(-2, dot, sq_i + sq_j)              (2*dot exact)
//   mask = d2 <= 9
//
// CONVERGED (R10 = R7 config, session optimum 40.29 us kernel time).
// Limiting resource: chip-wide LTS byte-throughput cap (path-independent).
// 268.4 MB output / 40.29 us = 6.66 TB/s == the cap; nothing else binds
// (issue 26%, fma 23%, occ 66%, DRAM 65%). Proven requirements:
//   - lane-contiguous 16 B/thread STG.128 (R9: strided stores -> +80% time)
//   - >=4 resident CTAs/SM (R2: single CTA -> +150% time)
//   - per-warp STG path beats TMA bulk drain here (R6 regression)
// Packed f32x2 math (PTX-only) keeps issue slack; bit-identical per-lane .rn.

#define NPTS 8192
#define JPT  4     // j-points per thread (= 2 packed lanes), one STG.128/row
#define TPB  256   // 1024 j-cols per block
#define IPB  16    // i-rows per block; grid = 8 * 512 = 4096

typedef unsigned long long u64;

__device__ __forceinline__ u64 pack2(float lo, float hi)
{
    u64 r; asm("mov.b64 %0, {%1, %2};" : "=l"(r) : "f"(lo), "f"(hi)); return r;
}
__device__ __forceinline__ u64 mul2(u64 a, u64 b)
{
    u64 r; asm("mul.rn.f32x2 %0, %1, %2;" : "=l"(r) : "l"(a), "l"(b)); return r;
}
__device__ __forceinline__ u64 add2(u64 a, u64 b)
{
    u64 r; asm("add.rn.f32x2 %0, %1, %2;" : "=l"(r) : "l"(a), "l"(b)); return r;
}
__device__ __forceinline__ u64 fma2(u64 a, u64 b, u64 c)
{
    u64 r; asm("fma.rn.f32x2 %0, %1, %2, %3;" : "=l"(r) : "l"(a), "l"(b), "l"(c)); return r;
}
__device__ __forceinline__ float set_le9(float a)
{
    float r; asm("set.le.f32.f32 %0, %1, 0f41100000;" : "=f"(r) : "f"(a)); return r;
}

__global__ __launch_bounds__(TPB, 6)
void radius_mask_kernel(const float* __restrict__ pos, float4* __restrict__ out)
{
    // per i-row, pre-packed broadcasts: [0]={x,x | y,y}  [1]={z,z | q,q}
    __shared__ ulonglong2 si2[IPB][2];

    const int t  = threadIdx.x;
    const int jb = blockIdx.x & 7;          // j-block: 8 per row-stripe
    const int ib = blockIdx.x >> 3;         // i-stripe: 512 of them
    const int i0 = ib * IPB;
    const int j0 = jb * (TPB * JPT) + t * JPT;

    if (t < IPB) {
        const int i = i0 + t;
        float x = pos[3 * i + 0];
        float y = pos[3 * i + 1];
        float z = pos[3 * i + 2];
        float q = __fadd_rn(__fadd_rn(__fmul_rn(x, x), __fmul_rn(y, y)),
                            __fmul_rn(z, z));
        si2[t][0] = make_ulonglong2(pack2(x, x), pack2(y, y));
        si2[t][1] = make_ulonglong2(pack2(z, z), pack2(q, q));
    }

    // 4 register-resident j-points as 2 packed lanes
    u64 xj2[2], yj2[2], zj2[2], sj2[2];
#pragma unroll
    for (int g = 0; g < 2; g++) {
        float xa = pos[3 * (j0 + 2 * g) + 0];
        float ya = pos[3 * (j0 + 2 * g) + 1];
        float za = pos[3 * (j0 + 2 * g) + 2];
        float xb = pos[3 * (j0 + 2 * g + 1) + 0];
        float yb = pos[3 * (j0 + 2 * g + 1) + 1];
        float zb = pos[3 * (j0 + 2 * g + 1) + 2];
        float qa = __fadd_rn(__fadd_rn(__fmul_rn(xa, xa), __fmul_rn(ya, ya)),
                             __fmul_rn(za, za));
        float qb = __fadd_rn(__fadd_rn(__fmul_rn(xb, xb), __fmul_rn(yb, yb)),
                             __fmul_rn(zb, zb));
        xj2[g] = pack2(xa, xb);
        yj2[g] = pack2(ya, yb);
        zj2[g] = pack2(za, zb);
        sj2[g] = pack2(qa, qb);
    }

    __syncthreads();

    const u64 NEG2 = 0xC0000000C0000000ull;   // {-2.0f, -2.0f}

    float4* dst = out + (size_t)i0 * (NPTS / 4) + (j0 >> 2);

#pragma unroll
    for (int ii = 0; ii < IPB; ii++) {
        const ulonglong2 A = si2[ii][0];      // {xx, yy}  LDS.128 broadcast
        const ulonglong2 B = si2[ii][1];      // {zz, qq}

        float v[JPT];
#pragma unroll
        for (int g = 0; g < 2; g++) {
            u64 dot = fma2(zj2[g], B.x, fma2(yj2[g], A.y, mul2(xj2[g], A.x)));
            u64 d2  = fma2(NEG2, dot, add2(B.y, sj2[g]));
            float lo, hi;
            asm("mov.b64 {%0, %1}, %2;" : "=f"(lo), "=f"(hi) : "l"(d2));
            v[2 * g + 0] = set_le9(lo);
            v[2 * g + 1] = set_le9(hi);
        }
        *dst = make_float4(v[0], v[1], v[2], v[3]);
        dst += NPTS / 4;
    }
}

extern "C" void kernel_launch(void* const* d_in, const int* in_sizes, int n_in,
                              void* d_out, int out_size)
{
    const float* pos = (const float*)d_in[0];
    float4* out = (float4*)d_out;
    radius_mask_kernel<<<(NPTS / (TPB * JPT)) * (NPTS / IPB), TPB>>>(pos, out);
}